// round 13
// baseline (speedup 1.0000x reference)
#include <cuda_runtime.h>
#include <cuda_bf16.h>

// SoftEmbeddedDecisionRules: balanced binary hierarchy over C=1024 classes.
// Two warps per row (512 classes each) to halve per-warp register state and
// raise occupancy. Lane L owns chunk L (4 classes) of each of the warp's 4
// half-spans -> all LDG.128/STG.128 perfectly coalesced. seg 1/2 lane-local;
// seg 4..64 shfl butterfly; seg 128/256 warp-local lane-uniform; seg 512 via
// a 2-float smem exchange between the row's warp pair (sigmoid symmetry:
// each warp computes sig((S_own-S_other)/1024), factors sum to 1 exactly).
// sigmoid(x/seg) = 0.5*tanh(x/(2seg)) + 0.5 — one MUFU per sigmoid.

#define BATCH_N 32768
#define NCLASS 1024

__device__ __forceinline__ float sigmoid_scaled(float d, float inv2seg) {
    float t;
    asm("tanh.approx.f32 %0, %1;" : "=f"(t) : "f"(d * inv2seg));
    return fmaf(0.5f, t, 0.5f);
}

__global__ void __launch_bounds__(256, 5)
soft_tree_kernel(const float* __restrict__ in, float* __restrict__ out) {
    __shared__ float sx[4][2];   // per-row warp-pair exchange (4 rows/block)

    const int tid   = threadIdx.x;
    const int wib   = tid >> 5;                 // warp in block (0..7)
    const int lane  = tid & 31;
    const int rowib = wib >> 1;                 // row in block (0..3)
    const int half  = wib & 1;                  // which 512-class half
    const int row   = blockIdx.x * 4 + rowib;

    // warp's 4 half-spans are global half-spans half*4 .. half*4+3
    const float4* gin  = reinterpret_cast<const float4*>(in  + (size_t)row * NCLASS)
                         + half * 128;          // 4 half-spans * 32 chunks
    float4*       gout = reinterpret_cast<float4*>(out + (size_t)row * NCLASS)
                         + half * 128;

    float fl0[4], fl1[4];  // leaf factors per owned chunk
    float a2[4];           // seg=2 factor per chunk
    float Bf[4];           // butterfly product seg 4..64
    float H[4];            // 128-sums (lane-uniform)

#pragma unroll
    for (int s = 0; s < 4; s++) {
        float4 q = gin[s * 32 + lane];          // coalesced

        fl0[s] = sigmoid_scaled(q.x - q.y, 0.5f);
        fl1[s] = sigmoid_scaled(q.z - q.w, 0.5f);

        float t0 = q.x + q.y, t1 = q.z + q.w;
        a2[s] = sigmoid_scaled(t0 - t1, 0.25f);

        float u = t0 + t1;                      // lane's 4-sum
        float B, o;
        o = __shfl_xor_sync(0xffffffffu, u, 1);
        B  = sigmoid_scaled(u - o, 1.0f / 8.0f);    u += o;
        o = __shfl_xor_sync(0xffffffffu, u, 2);
        B *= sigmoid_scaled(u - o, 1.0f / 16.0f);   u += o;
        o = __shfl_xor_sync(0xffffffffu, u, 4);
        B *= sigmoid_scaled(u - o, 1.0f / 32.0f);   u += o;
        o = __shfl_xor_sync(0xffffffffu, u, 8);
        B *= sigmoid_scaled(u - o, 1.0f / 64.0f);   u += o;
        o = __shfl_xor_sync(0xffffffffu, u, 16);
        B *= sigmoid_scaled(u - o, 1.0f / 128.0f);  u += o;
        Bf[s] = B;
        H[s]  = u;                              // 128-sum, lane-uniform
    }

    // ---- warp-local top levels: seg = 128 (f), 256 (g) ----
    float f0 = sigmoid_scaled(H[0] - H[1], 1.0f / 256.0f);
    float f1 = sigmoid_scaled(H[2] - H[3], 1.0f / 256.0f);
    float Q0 = H[0] + H[1], Q1 = H[2] + H[3];
    float g0 = sigmoid_scaled(Q0 - Q1, 1.0f / 512.0f);
    float S  = Q0 + Q1;                         // this warp's 512-sum

    // ---- seg = 512: exchange S with partner warp via smem ----
    if (lane == 0) sx[rowib][half] = S;
    __syncthreads();
    float So = sx[rowib][half ^ 1];
    float top = sigmoid_scaled(S - So, 1.0f / 1024.0f);  // factors sum to 1

    // path products for the warp's 4 half-spans
    float i0 = top * g0, i1 = top - i0;
    float T[4];
    T[0] = i0 * f0;  T[1] = i0 - T[0];
    T[2] = i1 * f1;  T[3] = i1 - T[2];

    // ---- downsweep + coalesced store ----
#pragma unroll
    for (int s = 0; s < 4; s++) {
        float P  = T[s] * Bf[s];
        float p0 = P * a2[s];
        float p1 = P - p0;

        float4 w;
        w.x = p0 * fl0[s];  w.y = p0 - w.x;
        w.z = p1 * fl1[s];  w.w = p1 - w.z;
        gout[s * 32 + lane] = w;                // coalesced
    }
}

extern "C" void kernel_launch(void* const* d_in, const int* in_sizes, int n_in,
                              void* d_out, int out_size) {
    (void)in_sizes; (void)n_in; (void)out_size;
    const float* in = (const float*)d_in[0];
    float* out = (float*)d_out;
    // 32768 rows, 2 warps per row, 8 warps per block -> 4 rows/block, 8192 blocks
    soft_tree_kernel<<<BATCH_N / 4, 256>>>(in, out);
}